// round 15
// baseline (speedup 1.0000x reference)
#include <cuda_runtime.h>
#include <cuda_fp16.h>
#include <cstdint>
#include <math.h>

// Problem constants
#define B_    2
#define T_    2048
#define D_    1024
#define H_    16
#define DH_   64
#define WIN_  256
#define E3_   3072          // 3*H*Dh
#define M_    (B_ * T_)     // 4096

// Scratch (static device globals — allocation-free per harness rules)
__device__ __half g_qkvh[(size_t)M_ * E3_];    // [4096,3072] fp16, natural
__device__ __half g_atth[(size_t)M_ * D_];     // [4096,1024] fp16, natural
__device__ __half g_xh[(size_t)M_ * D_];       // fp16 x (natural)
__device__ __half g_wqh[(size_t)E3_ * D_];     // fp16 w_qkv (natural)
__device__ __half g_woh[(size_t)D_ * D_];      // fp16 w_out (natural)

// ===========================================================================
// Helpers
// ===========================================================================
__device__ __forceinline__ uint32_t smem_u32(const void* p) {
    uint32_t a;
    asm("{ .reg .u64 t; cvta.to.shared.u64 t, %1; cvt.u32.u64 %0, t; }" : "=r"(a) : "l"(p));
    return a;
}
__device__ __forceinline__ void cp_async16(uint32_t saddr, const void* gptr) {
    asm volatile("cp.async.cg.shared.global [%0], [%1], 16;" :: "r"(saddr), "l"(gptr));
}
#define CP_COMMIT() asm volatile("cp.async.commit_group;" ::: "memory")
#define CP_WAIT0()  asm volatile("cp.async.wait_group 0;" ::: "memory")

// fp16 mma: m16n8k16, fp32 accumulate
__device__ __forceinline__ void mma_f16(float* c, const uint32_t* a, const uint32_t* b) {
    asm volatile(
        "mma.sync.aligned.m16n8k16.row.col.f32.f16.f16.f32 "
        "{%0,%1,%2,%3}, {%4,%5,%6,%7}, {%8,%9}, {%0,%1,%2,%3};"
        : "+f"(c[0]), "+f"(c[1]), "+f"(c[2]), "+f"(c[3])
        : "r"(a[0]), "r"(a[1]), "r"(a[2]), "r"(a[3]), "r"(b[0]), "r"(b[1]));
}
// ldmatrix x4 (non-transposed / transposed)
__device__ __forceinline__ void ldsm_x4(uint32_t& a0, uint32_t& a1,
                                        uint32_t& a2, uint32_t& a3, uint32_t addr) {
    asm volatile("ldmatrix.sync.aligned.m8n8.x4.shared.b16 {%0,%1,%2,%3}, [%4];"
                 : "=r"(a0), "=r"(a1), "=r"(a2), "=r"(a3) : "r"(addr));
}
__device__ __forceinline__ void ldsm_x4_t(uint32_t& a0, uint32_t& a1,
                                          uint32_t& a2, uint32_t& a3, uint32_t addr) {
    asm volatile("ldmatrix.sync.aligned.m8n8.x4.trans.shared.b16 {%0,%1,%2,%3}, [%4];"
                 : "=r"(a0), "=r"(a1), "=r"(a2), "=r"(a3) : "r"(addr));
}
__device__ __forceinline__ uint32_t h2u(__half2 h) { return *(uint32_t*)&h; }

// Fused fp32 -> fp16 convert (natural layout), all three operands, 1 launch.
#define NX16 (M_ * D_ / 16)
#define NW16 (E3_ * D_ / 16)
#define NO16 (D_ * D_ / 16)
__global__ void preround_all(const float* __restrict__ x,  const float* __restrict__ wq,
                             const float* __restrict__ wo, __half* __restrict__ xh,
                             __half* __restrict__ wqh,     __half* __restrict__ woh) {
    int i = blockIdx.x * blockDim.x + threadIdx.x;
    const float* s; __half* d; int j;
    if (i < NX16)             { s = x;  d = xh;  j = i; }
    else if (i < NX16 + NW16) { s = wq; d = wqh; j = i - NX16; }
    else if (i < NX16 + NW16 + NO16) { s = wo; d = woh; j = i - NX16 - NW16; }
    else return;
    const float4 v0 = ((const float4*)s)[4 * j + 0];
    const float4 v1 = ((const float4*)s)[4 * j + 1];
    const float4 v2 = ((const float4*)s)[4 * j + 2];
    const float4 v3 = ((const float4*)s)[4 * j + 3];
    __half2* o = (__half2*)(d + 16 * (size_t)j);
    o[0] = __floats2half2_rn(v0.x, v0.y);
    o[1] = __floats2half2_rn(v0.z, v0.w);
    o[2] = __floats2half2_rn(v1.x, v1.y);
    o[3] = __floats2half2_rn(v1.z, v1.w);
    o[4] = __floats2half2_rn(v2.x, v2.y);
    o[5] = __floats2half2_rn(v2.z, v2.w);
    o[6] = __floats2half2_rn(v3.x, v3.y);
    o[7] = __floats2half2_rn(v3.z, v3.w);
}

// ===========================================================================
// fp16 warp-MMA NT GEMM, NATURAL layout, ldmatrix fragment loads.
// BK=32, PITCH=72 halves (144B: LDSM phases conflict-free), block 128x128,
// 8 warps, 64x32 warp tile, 2 CTA/SM, 2-stage cp.async, 1 barrier/iter.
// C[m,n] = sum_k A[m,k]*B[n,k], fp32 accumulate.
// ===========================================================================
#define BM 128
#define BN 128
#define BK 32
#define PITCH 72                                   // halves/row: 64... (BK=32 data + pad)
#define STAGE_HALVES (2 * 128 * PITCH)             // A tile then B tile = 18432 halves
#define GEMM_SMEM (2 * STAGE_HALVES * 2)           // 73728 B

template <bool OUTH>
__global__ __launch_bounds__(256, 2) void gemm_tc(const __half* __restrict__ A,
                                                  const __half* __restrict__ B,
                                                  void* __restrict__ Cv,
                                                  int Ndim, int Kdim) {
    extern __shared__ __align__(16) __half smh[];
    const uint32_t sbase = smem_u32(smh);

    const int tid  = threadIdx.x;
    const int wid  = tid >> 5;
    const int lane = tid & 31;
    const int g    = lane >> 2;
    const int tg   = lane & 3;
    const int m0   = blockIdx.y * BM;
    const int n0   = blockIdx.x * BN;
    const int wm   = wid & 1;
    const int wn   = wid >> 1;

    // Staging: 4 threads per 32-half row (4 x 16B chunks); 64 rows/pass x2.
    const int lr = tid >> 2;
    const int lf = tid & 3;
    const uint32_t sa0 = sbase + (lr * PITCH + lf * 8) * 2;
    const uint32_t sb0 = sa0 + 128 * PITCH * 2;
    const __half* Ap0 = A + (size_t)(m0 + lr) * Kdim + lf * 8;
    const __half* Bp0 = B + (size_t)(n0 + lr) * Kdim + lf * 8;

    // ldmatrix lane->address components
    const int arow = ((lane >> 3) & 1) * 8 + (lane & 7);  // A: bit3 -> +8 rows
    const int acol = (lane >> 4) * 8;                     // A: bit4 -> k-half
    const int brow = (lane >> 4) * 8 + (lane & 7);        // B: bit4 -> +8 n-rows
    const int bcol = ((lane >> 3) & 1) * 8;               // B: bit3 -> k-half

    float c[4][4][4];
#pragma unroll
    for (int mt = 0; mt < 4; mt++)
#pragma unroll
        for (int nt = 0; nt < 4; nt++)
#pragma unroll
            for (int i = 0; i < 4; i++) c[mt][nt][i] = 0.f;

    const int NK = Kdim / BK;

    // Prologue: stage 0
    {
#pragma unroll
        for (int u = 0; u < 2; u++) {
            cp_async16(sa0 + u * 64 * PITCH * 2, Ap0 + (size_t)u * 64 * Kdim);
            cp_async16(sb0 + u * 64 * PITCH * 2, Bp0 + (size_t)u * 64 * Kdim);
        }
        CP_COMMIT();
    }

    for (int kt = 0; kt < NK; kt++) {
        CP_WAIT0();
        __syncthreads();          // tile kt landed; everyone past tile kt-1

        if (kt + 1 < NK) {        // overlap: stage kt+1 while computing kt
            const uint32_t off = (uint32_t)((kt + 1) & 1) * STAGE_HALVES * 2;
            const int kc = (kt + 1) * BK;
#pragma unroll
            for (int u = 0; u < 2; u++) {
                cp_async16(sa0 + off + u * 64 * PITCH * 2, Ap0 + kc + (size_t)u * 64 * Kdim);
                cp_async16(sb0 + off + u * 64 * PITCH * 2, Bp0 + kc + (size_t)u * 64 * Kdim);
            }
            CP_COMMIT();
        }

        const uint32_t aS = sbase + (uint32_t)(kt & 1) * STAGE_HALVES * 2;
        const uint32_t bS = aS + 128 * PITCH * 2;

#pragma unroll
        for (int kp = 0; kp < 2; kp++) {            // two k16 steps per BK=32
            const int ko = kp * 16;
            uint32_t af[4][4];
#pragma unroll
            for (int mt = 0; mt < 4; mt++)
                ldsm_x4(af[mt][0], af[mt][1], af[mt][2], af[mt][3],
                        aS + ((uint32_t)(wm * 64 + mt * 16 + arow) * PITCH + ko + acol) * 2);
#pragma unroll
            for (int ntp = 0; ntp < 2; ntp++) {
                uint32_t r0, r1, r2, r3;
                ldsm_x4(r0, r1, r2, r3,
                        bS + ((uint32_t)(wn * 32 + ntp * 16 + brow) * PITCH + ko + bcol) * 2);
                uint32_t b0[2] = {r0, r1};
                uint32_t b1[2] = {r2, r3};
#pragma unroll
                for (int mt = 0; mt < 4; mt++) {
                    mma_f16(c[mt][2 * ntp + 0], af[mt], b0);
                    mma_f16(c[mt][2 * ntp + 1], af[mt], b1);
                }
            }
        }
    }

    // Epilogue (natural column order)
#pragma unroll
    for (int mt = 0; mt < 4; mt++) {
        const int row = m0 + wm * 64 + mt * 16 + g;
#pragma unroll
        for (int nt = 0; nt < 4; nt++) {
            const int col = n0 + wn * 32 + nt * 8 + 2 * tg;
            if (OUTH) {
                __half* C = (__half*)Cv;
                *(__half2*)(C + (size_t)row * Ndim + col) =
                    __floats2half2_rn(c[mt][nt][0], c[mt][nt][1]);
                *(__half2*)(C + (size_t)(row + 8) * Ndim + col) =
                    __floats2half2_rn(c[mt][nt][2], c[mt][nt][3]);
            } else {
                float* C = (float*)Cv;
                *(float2*)(C + (size_t)row * Ndim + col) =
                    make_float2(c[mt][nt][0], c[mt][nt][1]);
                *(float2*)(C + (size_t)(row + 8) * Ndim + col) =
                    make_float2(c[mt][nt][2], c[mt][nt][3]);
            }
        }
    }
}

// ===========================================================================
// Sliding-window attention (round-14 proven version; epilogue now NATURAL).
// ===========================================================================
#define AQ 128
#define KP2 72
#define VPN 72
#define PP2 72
#define KCH2 (64 * KP2)
#define VCH2 (64 * VPN)
#define PS2OFF (2 * KCH2 + 2 * VCH2)
#define ATT_SMEM ((PS2OFF + 128 * PP2) * 2)   // 55296 B

__global__ __launch_bounds__(256, 2) void attn_mma(const __half* __restrict__ qkv,
                                                   __half* __restrict__ outp) {
    extern __shared__ __align__(16) __half smh[];
    const uint32_t sbase = smem_u32(smh);
    __half* Pp = smh + PS2OFF;

    const int tid  = threadIdx.x;
    const int wid  = tid >> 5;
    const int lane = tid & 31;
    const int g    = lane >> 2;
    const int tg   = lane & 3;
    const int q0   = blockIdx.x * AQ;
    const int h    = blockIdx.y;
    const int b    = blockIdx.z;
    const int qw   = q0 + wid * 16;

    const __half* base  = qkv + (size_t)b * T_ * E3_ + h * DH_;
    const __half* baseK = base + D_;
    const __half* baseV = base + 2 * D_;

    uint32_t qa[4][4];
    {
        const __half2 sc2 = __half2half2(__float2half_rn(0.125f));
        const __half* Qr0 = base + (size_t)(qw + g) * E3_;
        const __half* Qr1 = base + (size_t)(qw + 8 + g) * E3_;
#pragma unroll
        for (int ks = 0; ks < 4; ks++) {
            const int ko = ks * 16 + 2 * tg;
            qa[ks][0] = h2u(__hmul2(*(const __half2*)(Qr0 + ko), sc2));
            qa[ks][1] = h2u(__hmul2(*(const __half2*)(Qr1 + ko), sc2));
            qa[ks][2] = h2u(__hmul2(*(const __half2*)(Qr0 + ko + 8), sc2));
            qa[ks][3] = h2u(__hmul2(*(const __half2*)(Qr1 + ko + 8), sc2));
        }
    }

    float O[8][4];
#pragma unroll
    for (int nt = 0; nt < 8; nt++)
#pragma unroll
        for (int i = 0; i < 4; i++) O[nt][i] = 0.f;
    float mrow[2] = {-1e30f, -1e30f};
    float lrow[2] = {0.f, 0.f};

    const int c_lo = (q0 > 255 ? q0 - 255 : 0) >> 6;
    const int c_hi = (q0 + AQ - 1) >> 6;

    const int kr = tid >> 2;
    const int kf = tid & 3;
    auto issueKV = [&](int c, int s) {
        const int k0 = c << 6;
        const uint32_t kb = sbase + (uint32_t)s * KCH2 * 2;
        const uint32_t vb = sbase + (2 * KCH2 + (uint32_t)s * VCH2) * 2;
        const __half* srcK = baseK + (size_t)(k0 + kr) * E3_;
        const __half* srcV = baseV + (size_t)(k0 + kr) * E3_;
        cp_async16(kb + (kr * KP2 + kf * 8) * 2, srcK + kf * 8);
        cp_async16(kb + (kr * KP2 + (kf + 4) * 8) * 2, srcK + (kf + 4) * 8);
        cp_async16(vb + (kr * VPN + kf * 8) * 2, srcV + kf * 8);
        cp_async16(vb + (kr * VPN + (kf + 4) * 8) * 2, srcV + (kf + 4) * 8);
        CP_COMMIT();
    };

    const int ltile = lane >> 3;
    const int lrow8 = lane & 7;
    const int vk = (ltile & 1) * 8 + lrow8;
    const int vd = (ltile >> 1) * 8;

    issueKV(c_lo, 0);

    for (int c = c_lo; c <= c_hi; c++) {
        const int k0 = c << 6;
        const int st = (c - c_lo) & 1;
        CP_WAIT0();
        __syncthreads();
        if (c < c_hi) issueKV(c + 1, st ^ 1);

        const __half* Kb = smh + st * KCH2;
        const uint32_t vbase = sbase + (2 * KCH2 + (uint32_t)st * VCH2) * 2;

        const bool active = !(k0 > qw + 15 || k0 < qw - 318);
        if (active) {
            float s[8][4];
#pragma unroll
            for (int nt = 0; nt < 8; nt++)
#pragma unroll
                for (int i = 0; i < 4; i++) s[nt][i] = 0.f;

#pragma unroll
            for (int ks = 0; ks < 4; ks++) {
#pragma unroll
                for (int nt = 0; nt < 8; nt++) {
                    const __half* kp = Kb + (nt * 8 + g) * KP2 + ks * 16 + 2 * tg;
                    uint32_t bf[2] = {*(const uint32_t*)kp, *(const uint32_t*)(kp + 8)};
                    mma_f16(s[nt], qa[ks], bf);
                }
            }

#pragma unroll
            for (int nt = 0; nt < 8; nt++) {
#pragma unroll
                for (int p = 0; p < 2; p++) {
#pragma unroll
                    for (int j = 0; j < 2; j++) {
                        const int qr = qw + g + 8 * p;
                        const int kc = k0 + nt * 8 + 2 * tg + j;
                        const int d  = qr - kc;
                        if (!(d >= 0 && d < WIN_)) s[nt][p * 2 + j] = -1e30f;
                    }
                }
            }

#pragma unroll
            for (int p = 0; p < 2; p++) {
                float mx = -1e30f;
#pragma unroll
                for (int nt = 0; nt < 8; nt++) {
                    mx = fmaxf(mx, s[nt][p * 2 + 0]);
                    mx = fmaxf(mx, s[nt][p * 2 + 1]);
                }
                mx = fmaxf(mx, __shfl_xor_sync(0xffffffffu, mx, 1));
                mx = fmaxf(mx, __shfl_xor_sync(0xffffffffu, mx, 2));
                const float mnew = fmaxf(mrow[p], mx);
                float sum = 0.f;
#pragma unroll
                for (int nt = 0; nt < 8; nt++) {
#pragma unroll
                    for (int j = 0; j < 2; j++) {
                        const float v = s[nt][p * 2 + j];
                        const float pv = (v < -5e29f) ? 0.f : __expf(v - mnew);
                        s[nt][p * 2 + j] = pv;
                        sum += pv;
                    }
                }
                sum += __shfl_xor_sync(0xffffffffu, sum, 1);
                sum += __shfl_xor_sync(0xffffffffu, sum, 2);
                const float alpha = (mrow[p] < -5e29f) ? 0.f : __expf(mrow[p] - mnew);
                lrow[p] = lrow[p] * alpha + sum;
                mrow[p] = mnew;
#pragma unroll
                for (int nt = 0; nt < 8; nt++) {
                    O[nt][p * 2 + 0] *= alpha;
                    O[nt][p * 2 + 1] *= alpha;
                }
            }

            const int pr0 = wid * 16 + g;
            const int pr1 = pr0 + 8;
#pragma unroll
            for (int nt = 0; nt < 8; nt++) {
                *(__half2*)(Pp + pr0 * PP2 + nt * 8 + 2 * tg) =
                    __floats2half2_rn(s[nt][0], s[nt][1]);
                *(__half2*)(Pp + pr1 * PP2 + nt * 8 + 2 * tg) =
                    __floats2half2_rn(s[nt][2], s[nt][3]);
            }
            __syncwarp();

#pragma unroll
            for (int ks = 0; ks < 4; ks++) {
                const __half* pp0 = Pp + pr0 * PP2 + ks * 16 + 2 * tg;
                const __half* pp1 = Pp + pr1 * PP2 + ks * 16 + 2 * tg;
                uint32_t a[4] = {*(const uint32_t*)pp0, *(const uint32_t*)pp1,
                                 *(const uint32_t*)(pp0 + 8), *(const uint32_t*)(pp1 + 8)};
#pragma unroll
                for (int ntp = 0; ntp < 4; ntp++) {
                    uint32_t r0, r1, r2, r3;
                    const uint32_t addr = vbase +
                        ((uint32_t)(ks * 16 + vk) * VPN + (uint32_t)(ntp * 16 + vd)) * 2;
                    ldsm_x4_t(r0, r1, r2, r3, addr);
                    uint32_t b0[2] = {r0, r1};
                    mma_f16(O[2 * ntp + 0], a, b0);
                    uint32_t b1[2] = {r2, r3};
                    mma_f16(O[2 * ntp + 1], a, b1);
                }
            }
        }
    }

    // Epilogue: normalize, fp16, NATURAL store (gemm2 reads natural now).
    const float inv0 = 1.0f / lrow[0];
    const float inv1 = 1.0f / lrow[1];
    const int row0 = b * T_ + qw + g;
    const int row1 = row0 + 8;
#pragma unroll
    for (int nt = 0; nt < 8; nt++) {
        const int col = h * DH_ + nt * 8 + 2 * tg;
        *(__half2*)(outp + (size_t)row0 * D_ + col) =
            __floats2half2_rn(O[nt][0] * inv0, O[nt][1] * inv0);
        *(__half2*)(outp + (size_t)row1 * D_ + col) =
            __floats2half2_rn(O[nt][2] * inv1, O[nt][3] * inv1);
    }
}

// ---------------------------------------------------------------------------
// Host launcher
// ---------------------------------------------------------------------------
extern "C" void kernel_launch(void* const* d_in, const int* in_sizes, int n_in,
                              void* d_out, int out_size) {
    (void)in_sizes; (void)n_in; (void)out_size;
    const float* x     = (const float*)d_in[0];   // [B,T,D]
    const float* w_qkv = (const float*)d_in[1];   // [3072,1024]
    const float* w_out = (const float*)d_in[2];   // [1024,1024]
    float* out = (float*)d_out;                   // [B,T,D]

    __half *qkvh, *attbuf, *xh, *wqh, *woh;
    cudaGetSymbolAddress((void**)&qkvh,   g_qkvh);
    cudaGetSymbolAddress((void**)&attbuf, g_atth);
    cudaGetSymbolAddress((void**)&xh,     g_xh);
    cudaGetSymbolAddress((void**)&wqh,    g_wqh);
    cudaGetSymbolAddress((void**)&woh,    g_woh);

    cudaFuncSetAttribute(gemm_tc<true>,  cudaFuncAttributeMaxDynamicSharedMemorySize, GEMM_SMEM);
    cudaFuncSetAttribute(gemm_tc<false>, cudaFuncAttributeMaxDynamicSharedMemorySize, GEMM_SMEM);
    cudaFuncSetAttribute(attn_mma, cudaFuncAttributeMaxDynamicSharedMemorySize, ATT_SMEM);

    // 0) Fused fp32->fp16 convert of all GEMM inputs (natural layout)
    {
        const int total = NX16 + NW16 + NO16;    // 524288
        preround_all<<<(total + 255) / 256, 256>>>(x, w_qkv, w_out, xh, wqh, woh);
    }

    // 1) QKV projection (fp16 mma + ldmatrix; fp16 natural output)
    gemm_tc<true><<<dim3(E3_ / BN, M_ / BM), 256, GEMM_SMEM>>>(xh, wqh, qkvh, E3_, D_);

    // 2) Sliding-window attention (fp16 mma; writes fp16 natural g_att)
    attn_mma<<<dim3(T_ / AQ, H_, B_), 256, ATT_SMEM>>>(qkvh, attbuf);

    // 3) Output projection (fp16 mma + ldmatrix; final fp32 output)
    gemm_tc<false><<<dim3(D_ / BN, M_ / BM), 256, GEMM_SMEM>>>(attbuf, woh, out, D_, D_);
}

// round 16
// speedup vs baseline: 1.0342x; 1.0342x over previous
#include <cuda_runtime.h>
#include <cuda_fp16.h>
#include <cstdint>
#include <math.h>

// Problem constants
#define B_    2
#define T_    2048
#define D_    1024
#define H_    16
#define DH_   64
#define WIN_  256
#define E3_   3072          // 3*H*Dh
#define M_    (B_ * T_)     // 4096

// Scratch (static device globals — allocation-free per harness rules)
__device__ __half g_qkvh[(size_t)M_ * E3_];    // [4096,3072] fp16, natural
__device__ __half g_atth[(size_t)M_ * D_];     // [4096,1024] fp16, 16-permuted
__device__ __half g_xh[(size_t)M_ * D_];       // fp16 + 16-permuted x
__device__ __half g_wqh[(size_t)E3_ * D_];     // fp16 + 16-permuted w_qkv
__device__ __half g_woh[(size_t)D_ * D_];      // fp16 + 16-permuted w_out

// ===========================================================================
// Helpers
// ===========================================================================
__device__ __forceinline__ uint32_t smem_u32(const void* p) {
    uint32_t a;
    asm("{ .reg .u64 t; cvta.to.shared.u64 t, %1; cvt.u32.u64 %0, t; }" : "=r"(a) : "l"(p));
    return a;
}
__device__ __forceinline__ void cp_async16(uint32_t saddr, const void* gptr) {
    asm volatile("cp.async.cg.shared.global [%0], [%1], 16;" :: "r"(saddr), "l"(gptr));
}
#define CP_COMMIT() asm volatile("cp.async.commit_group;" ::: "memory")
#define CP_WAIT0()  asm volatile("cp.async.wait_group 0;" ::: "memory")

// fp16 mma: m16n8k16, fp32 accumulate
__device__ __forceinline__ void mma_f16(float* c, const uint32_t* a, const uint32_t* b) {
    asm volatile(
        "mma.sync.aligned.m16n8k16.row.col.f32.f16.f16.f32 "
        "{%0,%1,%2,%3}, {%4,%5,%6,%7}, {%8,%9}, {%0,%1,%2,%3};"
        : "+f"(c[0]), "+f"(c[1]), "+f"(c[2]), "+f"(c[3])
        : "r"(a[0]), "r"(a[1]), "r"(a[2]), "r"(a[3]), "r"(b[0]), "r"(b[1]));
}
// ldmatrix x4 (non-transposed / transposed)
__device__ __forceinline__ void ldsm_x4(uint32_t& a0, uint32_t& a1,
                                        uint32_t& a2, uint32_t& a3, uint32_t addr) {
    asm volatile("ldmatrix.sync.aligned.m8n8.x4.shared.b16 {%0,%1,%2,%3}, [%4];"
                 : "=r"(a0), "=r"(a1), "=r"(a2), "=r"(a3) : "r"(addr));
}
__device__ __forceinline__ void ldsm_x4_t(uint32_t& a0, uint32_t& a1,
                                          uint32_t& a2, uint32_t& a3, uint32_t addr) {
    asm volatile("ldmatrix.sync.aligned.m8n8.x4.trans.shared.b16 {%0,%1,%2,%3}, [%4];"
                 : "=r"(a0), "=r"(a1), "=r"(a2), "=r"(a3) : "r"(addr));
}
__device__ __forceinline__ uint32_t h2u(__half2 h) { return *(uint32_t*)&h; }

// Fused fp32 -> fp16 convert + 16-group k-permute, all three operands.
// Within each 16 k-group: dst[4t+0..3] = src[2t, 2t+1, 2t+8, 2t+9].
#define NX16 (M_ * D_ / 16)
#define NW16 (E3_ * D_ / 16)
#define NO16 (D_ * D_ / 16)
__global__ void preround_all(const float* __restrict__ x,  const float* __restrict__ wq,
                             const float* __restrict__ wo, __half* __restrict__ xh,
                             __half* __restrict__ wqh,     __half* __restrict__ woh) {
    int i = blockIdx.x * blockDim.x + threadIdx.x;
    const float* s; __half* d; int j;
    if (i < NX16)             { s = x;  d = xh;  j = i; }
    else if (i < NX16 + NW16) { s = wq; d = wqh; j = i - NX16; }
    else if (i < NX16 + NW16 + NO16) { s = wo; d = woh; j = i - NX16 - NW16; }
    else return;
    const float4 v0 = ((const float4*)s)[4 * j + 0];   // src[0..3]
    const float4 v1 = ((const float4*)s)[4 * j + 1];   // src[4..7]
    const float4 v2 = ((const float4*)s)[4 * j + 2];   // src[8..11]
    const float4 v3 = ((const float4*)s)[4 * j + 3];   // src[12..15]
    __half2* o = (__half2*)(d + 16 * (size_t)j);
    o[0] = __floats2half2_rn(v0.x, v0.y);   // dst[0,1]   = src[0,1]
    o[1] = __floats2half2_rn(v2.x, v2.y);   // dst[2,3]   = src[8,9]
    o[2] = __floats2half2_rn(v0.z, v0.w);   // dst[4,5]   = src[2,3]
    o[3] = __floats2half2_rn(v2.z, v2.w);   // dst[6,7]   = src[10,11]
    o[4] = __floats2half2_rn(v1.x, v1.y);   // dst[8,9]   = src[4,5]
    o[5] = __floats2half2_rn(v3.x, v3.y);   // dst[10,11] = src[12,13]
    o[6] = __floats2half2_rn(v1.z, v1.w);   // dst[12,13] = src[6,7]
    o[7] = __floats2half2_rn(v3.z, v3.w);   // dst[14,15] = src[14,15]
}

// ===========================================================================
// fp16 warp-MMA NT GEMM on 16-permuted inputs (ROUND-12/14 PROVEN VERSION).
// BK=32, PITCH=80, LDS.64 fragment loads, 2 CTA/SM, 2-stage cp.async.
// ===========================================================================
#define BM 128
#define BN 128
#define BK 32
#define PITCH 80
#define STAGE_HALVES (2 * 128 * PITCH)
#define GEMM_SMEM (2 * STAGE_HALVES * 2)           // 81920 B

template <bool OUTH>
__global__ __launch_bounds__(256, 2) void gemm_tc(const __half* __restrict__ A,
                                                  const __half* __restrict__ B,
                                                  void* __restrict__ Cv,
                                                  int Ndim, int Kdim) {
    extern __shared__ __align__(16) __half smh[];
    const uint32_t sbase = smem_u32(smh);

    const int tid  = threadIdx.x;
    const int wid  = tid >> 5;
    const int lane = tid & 31;
    const int g    = lane >> 2;
    const int tg   = lane & 3;
    const int m0   = blockIdx.y * BM;
    const int n0   = blockIdx.x * BN;
    const int wm   = wid & 1;
    const int wn   = wid >> 1;

    const int lr = tid >> 2;     // staging row 0..63 (x2 via +64 offset)
    const int lf = tid & 3;      // 16B chunk within 32-half k-row

    const uint32_t sa0 = sbase + (lr * PITCH + lf * 8) * 2;
    const uint32_t sb0 = sa0 + 128 * PITCH * 2;
    const __half* Ap0 = A + (size_t)(m0 + lr) * Kdim + lf * 8;
    const __half* Bp0 = B + (size_t)(n0 + lr) * Kdim + lf * 8;

    float c[4][4][4];
#pragma unroll
    for (int mt = 0; mt < 4; mt++)
#pragma unroll
        for (int nt = 0; nt < 4; nt++)
#pragma unroll
            for (int i = 0; i < 4; i++) c[mt][nt][i] = 0.f;

    const int NK = Kdim / BK;

    {
#pragma unroll
        for (int u = 0; u < 2; u++) {
            cp_async16(sa0 + u * 64 * PITCH * 2, Ap0 + (size_t)u * 64 * Kdim);
            cp_async16(sb0 + u * 64 * PITCH * 2, Bp0 + (size_t)u * 64 * Kdim);
        }
        CP_COMMIT();
    }

    for (int kt = 0; kt < NK; kt++) {
        CP_WAIT0();
        __syncthreads();

        if (kt + 1 < NK) {
            const uint32_t off = (uint32_t)((kt + 1) & 1) * STAGE_HALVES * 2;
            const int kc = (kt + 1) * BK;
#pragma unroll
            for (int u = 0; u < 2; u++) {
                cp_async16(sa0 + off + u * 64 * PITCH * 2, Ap0 + kc + (size_t)u * 64 * Kdim);
                cp_async16(sb0 + off + u * 64 * PITCH * 2, Bp0 + kc + (size_t)u * 64 * Kdim);
            }
            CP_COMMIT();
        }

        const __half* Ab = smh + (kt & 1) * STAGE_HALVES;
        const __half* Bb = Ab + 128 * PITCH;

#pragma unroll
        for (int kp = 0; kp < 2; kp++) {
            const int ko = kp * 16 + 4 * tg;
            uint32_t af[4][4], bf[4][2];
#pragma unroll
            for (int mt = 0; mt < 4; mt++) {
                const int r = wm * 64 + mt * 16 + g;
                const uint2 u0 = *(const uint2*)(Ab + r * PITCH + ko);
                const uint2 u1 = *(const uint2*)(Ab + (r + 8) * PITCH + ko);
                af[mt][0] = u0.x;
                af[mt][1] = u1.x;
                af[mt][2] = u0.y;
                af[mt][3] = u1.y;
            }
#pragma unroll
            for (int nt = 0; nt < 4; nt++) {
                const int n = wn * 32 + nt * 8 + g;
                const uint2 q = *(const uint2*)(Bb + n * PITCH + ko);
                bf[nt][0] = q.x;
                bf[nt][1] = q.y;
            }
#pragma unroll
            for (int mt = 0; mt < 4; mt++)
#pragma unroll
                for (int nt = 0; nt < 4; nt++)
                    mma_f16(c[mt][nt], af[mt], bf[nt]);
        }
    }

    // Epilogue (natural column order)
#pragma unroll
    for (int mt = 0; mt < 4; mt++) {
        const int row = m0 + wm * 64 + mt * 16 + g;
#pragma unroll
        for (int nt = 0; nt < 4; nt++) {
            const int col = n0 + wn * 32 + nt * 8 + 2 * tg;
            if (OUTH) {
                __half* C = (__half*)Cv;
                *(__half2*)(C + (size_t)row * Ndim + col) =
                    __floats2half2_rn(c[mt][nt][0], c[mt][nt][1]);
                *(__half2*)(C + (size_t)(row + 8) * Ndim + col) =
                    __floats2half2_rn(c[mt][nt][2], c[mt][nt][3]);
            } else {
                float* C = (float*)Cv;
                *(float2*)(C + (size_t)row * Ndim + col) =
                    make_float2(c[mt][nt][0], c[mt][nt][1]);
                *(float2*)(C + (size_t)(row + 8) * Ndim + col) =
                    make_float2(c[mt][nt][2], c[mt][nt][3]);
            }
        }
    }
}

// ===========================================================================
// Sliding-window attention, ALL-fp16 mma. K/V staged natural (one cp.async
// group/chunk). K B-fragments via ldmatrix.x4; V via ldmatrix.x4.trans;
// P@V A-fragments taken DIRECTLY from the S C-fragments (no smem P buffer).
// ONE barrier per chunk, 2 CTA/SM. Epilogue: fp16 16-permuted g_att.
// ===========================================================================
#define AQ 128
#define KP2 72                       // halves per K row
#define VPN 72                       // halves per V (natural) row
#define KCH2 (64 * KP2)              // 4608 halves
#define VCH2 (64 * VPN)              // 4608
#define ATT_SMEM ((2 * KCH2 + 2 * VCH2) * 2)   // 36864 B

__global__ __launch_bounds__(256, 2) void attn_mma(const __half* __restrict__ qkv,
                                                   __half* __restrict__ outp) {
    extern __shared__ __align__(16) __half smh[];
    const uint32_t sbase = smem_u32(smh);

    const int tid  = threadIdx.x;
    const int wid  = tid >> 5;
    const int lane = tid & 31;
    const int g    = lane >> 2;
    const int tg   = lane & 3;
    const int q0   = blockIdx.x * AQ;
    const int h    = blockIdx.y;
    const int b    = blockIdx.z;
    const int qw   = q0 + wid * 16;

    const __half* base  = qkv + (size_t)b * T_ * E3_ + h * DH_;
    const __half* baseK = base + D_;
    const __half* baseV = base + 2 * D_;

    // Q fragments (fp16, scaled by 0.125 — exact power of two)
    uint32_t qa[4][4];
    {
        const __half2 sc2 = __half2half2(__float2half_rn(0.125f));
        const __half* Qr0 = base + (size_t)(qw + g) * E3_;
        const __half* Qr1 = base + (size_t)(qw + 8 + g) * E3_;
#pragma unroll
        for (int ks = 0; ks < 4; ks++) {
            const int ko = ks * 16 + 2 * tg;
            qa[ks][0] = h2u(__hmul2(*(const __half2*)(Qr0 + ko), sc2));
            qa[ks][1] = h2u(__hmul2(*(const __half2*)(Qr1 + ko), sc2));
            qa[ks][2] = h2u(__hmul2(*(const __half2*)(Qr0 + ko + 8), sc2));
            qa[ks][3] = h2u(__hmul2(*(const __half2*)(Qr1 + ko + 8), sc2));
        }
    }

    float O[8][4];
#pragma unroll
    for (int nt = 0; nt < 8; nt++)
#pragma unroll
        for (int i = 0; i < 4; i++) O[nt][i] = 0.f;
    float mrow[2] = {-1e30f, -1e30f};
    float lrow[2] = {0.f, 0.f};

    const int c_lo = (q0 > 255 ? q0 - 255 : 0) >> 6;
    const int c_hi = (q0 + AQ - 1) >> 6;

    // K+V staging: thread covers row kr, chunks kf and kf+4 (16B each)
    const int kr = tid >> 2;
    const int kf = tid & 3;
    auto issueKV = [&](int c, int s) {
        const int k0 = c << 6;
        const uint32_t kb = sbase + (uint32_t)s * KCH2 * 2;
        const uint32_t vb = sbase + (2 * KCH2 + (uint32_t)s * VCH2) * 2;
        const __half* srcK = baseK + (size_t)(k0 + kr) * E3_;
        const __half* srcV = baseV + (size_t)(k0 + kr) * E3_;
        cp_async16(kb + (kr * KP2 + kf * 8) * 2, srcK + kf * 8);
        cp_async16(kb + (kr * KP2 + (kf + 4) * 8) * 2, srcK + (kf + 4) * 8);
        cp_async16(vb + (kr * VPN + kf * 8) * 2, srcV + kf * 8);
        cp_async16(vb + (kr * VPN + (kf + 4) * 8) * 2, srcV + (kf + 4) * 8);
        CP_COMMIT();
    };

    // ldmatrix lane addressing
    const int ltile = lane >> 3;          // 0..3
    const int lrow8 = lane & 7;
    // V (trans): tiles = {k lo/hi} x {d lo/hi}
    const int vk = (ltile & 1) * 8 + lrow8;
    const int vd = (ltile >> 1) * 8;
    // K (non-trans): tiles = {k lo/hi} x {n +0/+8}
    const int kn = (ltile >> 1) * 8 + lrow8;   // n-row within 16
    const int kk = (ltile & 1) * 8;            // k-half

    issueKV(c_lo, 0);

    for (int c = c_lo; c <= c_hi; c++) {
        const int k0 = c << 6;
        const int st = (c - c_lo) & 1;
        CP_WAIT0();
        __syncthreads();                       // K/V(c) landed; compute(c-1) done
        if (c < c_hi) issueKV(c + 1, st ^ 1);

        const uint32_t kbase = sbase + (uint32_t)st * KCH2 * 2;
        const uint32_t vbase = sbase + (2 * KCH2 + (uint32_t)st * VCH2) * 2;

        const bool active = !(k0 > qw + 15 || k0 < qw - 318);
        if (active) {
            // S = Q @ K^T  (16 rows x 64 keys); K B-frags via ldmatrix.x4
            float s[8][4];
#pragma unroll
            for (int nt = 0; nt < 8; nt++)
#pragma unroll
                for (int i = 0; i < 4; i++) s[nt][i] = 0.f;

#pragma unroll
            for (int ks = 0; ks < 4; ks++) {
#pragma unroll
                for (int ntp = 0; ntp < 4; ntp++) {
                    uint32_t r0, r1, r2, r3;
                    const uint32_t addr = kbase +
                        ((uint32_t)(ntp * 16 + kn) * KP2 + (uint32_t)(ks * 16 + kk)) * 2;
                    ldsm_x4(r0, r1, r2, r3, addr);
                    uint32_t b0[2] = {r0, r1};
                    mma_f16(s[2 * ntp + 0], qa[ks], b0);
                    uint32_t b1[2] = {r2, r3};
                    mma_f16(s[2 * ntp + 1], qa[ks], b1);
                }
            }

            // Sliding causal window mask
#pragma unroll
            for (int nt = 0; nt < 8; nt++) {
#pragma unroll
                for (int p = 0; p < 2; p++) {
#pragma unroll
                    for (int j = 0; j < 2; j++) {
                        const int qr = qw + g + 8 * p;
                        const int kc = k0 + nt * 8 + 2 * tg + j;
                        const int d  = qr - kc;
                        if (!(d >= 0 && d < WIN_)) s[nt][p * 2 + j] = -1e30f;
                    }
                }
            }

            // Online softmax (fp32, quad-reduced)
#pragma unroll
            for (int p = 0; p < 2; p++) {
                float mx = -1e30f;
#pragma unroll
                for (int nt = 0; nt < 8; nt++) {
                    mx = fmaxf(mx, s[nt][p * 2 + 0]);
                    mx = fmaxf(mx, s[nt][p * 2 + 1]);
                }
                mx = fmaxf(mx, __shfl_xor_sync(0xffffffffu, mx, 1));
                mx = fmaxf(mx, __shfl_xor_sync(0xffffffffu, mx, 2));
                const float mnew = fmaxf(mrow[p], mx);
                float sum = 0.f;
#pragma unroll
                for (int nt = 0; nt < 8; nt++) {
#pragma unroll
                    for (int j = 0; j < 2; j++) {
                        const float v = s[nt][p * 2 + j];
                        const float pv = (v < -5e29f) ? 0.f : __expf(v - mnew);
                        s[nt][p * 2 + j] = pv;
                        sum += pv;
                    }
                }
                sum += __shfl_xor_sync(0xffffffffu, sum, 1);
                sum += __shfl_xor_sync(0xffffffffu, sum, 2);
                const float alpha = (mrow[p] < -5e29f) ? 0.f : __expf(mrow[p] - mnew);
                lrow[p] = lrow[p] * alpha + sum;
                mrow[p] = mnew;
#pragma unroll
                for (int nt = 0; nt < 8; nt++) {
                    O[nt][p * 2 + 0] *= alpha;
                    O[nt][p * 2 + 1] *= alpha;
                }
            }

            // O += P @ V : A-fragments DIRECTLY from S C-fragments (register),
            // V B-fragments via ldmatrix.x4.trans from natural V.
#pragma unroll
            for (int ks = 0; ks < 4; ks++) {
                uint32_t a[4];
                a[0] = h2u(__floats2half2_rn(s[2 * ks][0],     s[2 * ks][1]));
                a[1] = h2u(__floats2half2_rn(s[2 * ks][2],     s[2 * ks][3]));
                a[2] = h2u(__floats2half2_rn(s[2 * ks + 1][0], s[2 * ks + 1][1]));
                a[3] = h2u(__floats2half2_rn(s[2 * ks + 1][2], s[2 * ks + 1][3]));
#pragma unroll
                for (int ntp = 0; ntp < 4; ntp++) {
                    uint32_t r0, r1, r2, r3;
                    const uint32_t addr = vbase +
                        ((uint32_t)(ks * 16 + vk) * VPN + (uint32_t)(ntp * 16 + vd)) * 2;
                    ldsm_x4_t(r0, r1, r2, r3, addr);
                    uint32_t b0[2] = {r0, r1};
                    mma_f16(O[2 * ntp + 0], a, b0);
                    uint32_t b1[2] = {r2, r3};
                    mma_f16(O[2 * ntp + 1], a, b1);
                }
            }
        }
        // single barrier per chunk: next iteration's top barrier protects reuse
    }

    // Epilogue: normalize, fp16, 16-group permuted store for gemm2.
    const float inv0 = 1.0f / lrow[0];
    const float inv1 = 1.0f / lrow[1];
    const int row0 = b * T_ + qw + g;
    const int row1 = row0 + 8;
#pragma unroll
    for (int nt = 0; nt < 8; nt++) {
        const int colb = h * DH_ + (nt >> 1) * 16;
        const int d0 = 4 * tg + 2 * (nt & 1);
        *(__half2*)(outp + (size_t)row0 * D_ + colb + d0) =
            __floats2half2_rn(O[nt][0] * inv0, O[nt][1] * inv0);
        *(__half2*)(outp + (size_t)row1 * D_ + colb + d0) =
            __floats2half2_rn(O[nt][2] * inv1, O[nt][3] * inv1);
    }
}

// ---------------------------------------------------------------------------
// Host launcher
// ---------------------------------------------------------------------------
extern "C" void kernel_launch(void* const* d_in, const int* in_sizes, int n_in,
                              void* d_out, int out_size) {
    (void)in_sizes; (void)n_in; (void)out_size;
    const float* x     = (const float*)d_in[0];   // [B,T,D]
    const float* w_qkv = (const float*)d_in[1];   // [3072,1024]
    const float* w_out = (const float*)d_in[2];   // [1024,1024]
    float* out = (float*)d_out;                   // [B,T,D]

    __half *qkvh, *attbuf, *xh, *wqh, *woh;
    cudaGetSymbolAddress((void**)&qkvh,   g_qkvh);
    cudaGetSymbolAddress((void**)&attbuf, g_atth);
    cudaGetSymbolAddress((void**)&xh,     g_xh);
    cudaGetSymbolAddress((void**)&wqh,    g_wqh);
    cudaGetSymbolAddress((void**)&woh,    g_woh);

    cudaFuncSetAttribute(gemm_tc<true>,  cudaFuncAttributeMaxDynamicSharedMemorySize, GEMM_SMEM);
    cudaFuncSetAttribute(gemm_tc<false>, cudaFuncAttributeMaxDynamicSharedMemorySize, GEMM_SMEM);
    cudaFuncSetAttribute(attn_mma, cudaFuncAttributeMaxDynamicSharedMemorySize, ATT_SMEM);

    // 0) Fused fp32->fp16 convert + 16-group k-permute of all GEMM inputs
    {
        const int total = NX16 + NW16 + NO16;    // 524288
        preround_all<<<(total + 255) / 256, 256>>>(x, w_qkv, w_out, xh, wqh, woh);
    }

    // 1) QKV projection (fp16 mma; fp16 NATURAL output for attention)
    gemm_tc<true><<<dim3(E3_ / BN, M_ / BM), 256, GEMM_SMEM>>>(xh, wqh, qkvh, E3_, D_);

    // 2) Sliding-window attention (fp16 mma; writes fp16 16-permuted g_att)
    attn_mma<<<dim3(T_ / AQ, H_, B_), 256, ATT_SMEM>>>(qkvh, attbuf);

    // 3) Output projection (fp16 mma; final fp32 output)
    gemm_tc<false><<<dim3(D_ / BN, M_ / BM), 256, GEMM_SMEM>>>(attbuf, woh, out, D_, D_);
}